// round 17
// baseline (speedup 1.0000x reference)
#include <cuda_runtime.h>
#include <cuda_bf16.h>
#include <math.h>

// Problem constants
#define B_  64
#define T_  2048
#define O_  3
#define D_  512
#define M_  100000u
#define H_  4

// Tiling
#define NCH 16           // chunks per batch row (grid = 1024 CTAs)
#define TCH (T_ / NCH)   // 128 timesteps per chunk (== NT)
#define TW  8            // unmasked timesteps per tile
#define NT  128          // thread t owns dims [4t,4t+4); warp == head

// Chunk partial softmax state + completion counters
__device__ float g_m[B_ * NCH * H_];
__device__ float g_s[B_ * NCH * H_];
__device__ float g_acc[B_ * NCH * D_];
__device__ int   g_cnt[B_];            // zero-init; self-resetting each run

__global__ __launch_bounds__(NT, 4)
void fused_kernel(const int* __restrict__ tok,
                  const int* __restrict__ prv,
                  const int* __restrict__ mask,       // bool delivered as int32
                  const float* __restrict__ embed,
                  const float* __restrict__ engram,
                  const float* __restrict__ gate_logit,
                  const float* __restrict__ temp,
                  const float* __restrict__ salW,
                  const float* __restrict__ salb,
                  const float* __restrict__ gateW,
                  const float* __restrict__ gateb,
                  const float* __restrict__ rms_scale,
                  float* __restrict__ out)
{
    const int b = blockIdx.y;
    const int c = blockIdx.x;
    const int t = threadIdx.x;          // 0..127
    const int h = t >> 5;               // warp index == head
    const int lane = t & 31;

    __shared__ unsigned int stok[TCH + O_];
    __shared__ unsigned int cHash[(TCH + TW) * H_];  // compacted: idx*512 + h*128
    __shared__ unsigned int cEmb[TCH + TW];          // compacted: c0*512
    __shared__ float spart[2][TW][H_][H_];           // [parity][j][warp][head]
    __shared__ int   scnt[H_];
    __shared__ float sgl[H_], ssq[H_];
    __shared__ int   s_last;

    const int t0 = c * TCH;

    // Stage tokens (TCH + 3 entries)
    for (int i = t; i < TCH + O_; i += NT) {
        int u = t0 - O_ + i;
        stok[i] = (u < 0) ? (unsigned)prv[b * O_ + (O_ + u)]
                          : (unsigned)tok[b * T_ + u];
    }

    // ---- Mask compaction: one ballot per warp (TCH == NT) ----
    int mvv = (mask[b * T_ + t0 + t] != 0);
    unsigned bal = __ballot_sync(0xffffffffu, mvv);
    if (lane == 0) scnt[h] = __popc(bal);
    __syncthreads();   // scnt ready AND stok ready

    int base = 0;
    #pragma unroll
    for (int seg = 0; seg < H_; seg++) if (seg < h) base += scnt[seg];
    const int nv = scnt[0] + scnt[1] + scnt[2] + scnt[3];
    const int off = base + __popc(bal & ((1u << lane) - 1u));

    // ---- Hash precompute: each unmasked thread writes its compacted offsets ----
    if (mvv) {
        unsigned c0 = stok[t + 3];
        unsigned c1 = stok[t + 2];
        unsigned c2 = stok[t + 1];
        unsigned c3 = stok[t + 0];
        #pragma unroll
        for (int hh = 0; hh < H_; hh++) {
            unsigned p0 = 131u + (unsigned)hh * 1009u;
            unsigned p1 = p0 * 31u + 1u;
            unsigned p2 = p1 * 31u + 1u;
            unsigned p3 = p2 * 31u + 1u;
            unsigned idx = (c0 * p0 + c1 * p1 + c2 * p2 + c3 * p3) % M_;
            cHash[off * H_ + hh] = idx * (unsigned)D_ + (unsigned)(hh * 128);
        }
        cEmb[off] = c0 * (unsigned)D_;
    }
    if (t < TW) {   // safe padding (weights are forced to 0 for j >= nv)
        #pragma unroll
        for (int hh = 0; hh < H_; hh++) cHash[(nv + t) * H_ + hh] = 0;
        cEmb[nv + t] = 0;
    }
    __syncthreads();

    // Per-thread constants
    float4 gl = __ldg((const float4*)gate_logit + t);
    float4 g4;
    g4.x = 1.0f / (1.0f + __expf(-gl.x));
    g4.y = 1.0f / (1.0f + __expf(-gl.y));
    g4.z = 1.0f / (1.0f + __expf(-gl.z));
    g4.w = 1.0f / (1.0f + __expf(-gl.w));

    float4 Wr0 = __ldg((const float4*)salW + (t * 4 + 0));
    float4 Wr1 = __ldg((const float4*)salW + (t * 4 + 1));
    float4 Wr2 = __ldg((const float4*)salW + (t * 4 + 2));
    float4 Wr3 = __ldg((const float4*)salW + (t * 4 + 3));

    const float invT = 1.0f / (log1pf(__expf(temp[h])) + 0.3f);
    const float bias = salb[h];

    float  m = -1e30f, s = 0.0f;
    float4 acc = make_float4(0.f, 0.f, 0.f, 0.f);

    for (int tt = 0; tt < nv; tt += TW) {
        const int pb = (tt / TW) & 1;

        // ---- Phase A: batch-issue engram (L2-only) + embed (L1) loads ----
        // engram offset: cHash already includes h*128; this thread reads +lane*4
        // embed  offset: cEmb is row base only; this thread reads dim 4t (= h*128 + lane*4)
        float4 e[TW], bv[TW];
        #pragma unroll
        for (int j = 0; j < TW; j++) {
            unsigned eo = cHash[(tt + j) * H_ + h];
            unsigned bo = cEmb[tt + j];
            e[j]  = __ldcg((const float4*)(engram + eo) + lane);
            bv[j] = __ldg ((const float4*)(embed  + bo) + t);
        }

        // ---- Phase B: x in regs, logits via 9-shuffle role-split reduction ----
        #pragma unroll
        for (int j = 0; j < TW; j++) {
            float4 x4;
            x4.x = fmaf(e[j].x, g4.x, bv[j].x);
            x4.y = fmaf(e[j].y, g4.y, bv[j].y);
            x4.z = fmaf(e[j].z, g4.z, bv[j].z);
            x4.w = fmaf(e[j].w, g4.w, bv[j].w);
            e[j] = x4;

            float p0 = fmaf(x4.x, Wr0.x, fmaf(x4.y, Wr1.x, fmaf(x4.z, Wr2.x, x4.w * Wr3.x)));
            float p1 = fmaf(x4.x, Wr0.y, fmaf(x4.y, Wr1.y, fmaf(x4.z, Wr2.y, x4.w * Wr3.y)));
            float p2 = fmaf(x4.x, Wr0.z, fmaf(x4.y, Wr1.z, fmaf(x4.z, Wr2.z, x4.w * Wr3.z)));
            float p3 = fmaf(x4.x, Wr0.w, fmaf(x4.y, Wr1.w, fmaf(x4.z, Wr2.w, x4.w * Wr3.w)));
            // role-split: offset 16 (4 shuffles)
            float t0s = __shfl_xor_sync(0xffffffffu, p0, 16);
            float t1s = __shfl_xor_sync(0xffffffffu, p1, 16);
            float t2s = __shfl_xor_sync(0xffffffffu, p2, 16);
            float t3s = __shfl_xor_sync(0xffffffffu, p3, 16);
            bool hi16 = (lane & 16) != 0;
            float q0 = hi16 ? (p2 + t2s) : (p0 + t0s);
            float q1 = hi16 ? (p3 + t3s) : (p1 + t1s);
            // offset 8 (2 shuffles)
            float u0 = __shfl_xor_sync(0xffffffffu, q0, 8);
            float u1 = __shfl_xor_sync(0xffffffffu, q1, 8);
            float v = (lane & 8) ? (q1 + u1) : (q0 + u0);
            // finish within octet (3 shuffles); octet o holds head o
            v += __shfl_xor_sync(0xffffffffu, v, 4);
            v += __shfl_xor_sync(0xffffffffu, v, 2);
            v += __shfl_xor_sync(0xffffffffu, v, 1);
            if ((lane & 7) == 0) spart[pb][j][h][lane >> 3] = v;
        }
        __syncthreads();

        // ---- Phase C: tile-level softmax update ----
        float l[TW]; float lm = -3e38f;
        #pragma unroll
        for (int j = 0; j < TW; j++) {
            float lg = spart[pb][j][0][h] + spart[pb][j][1][h]
                     + spart[pb][j][2][h] + spart[pb][j][3][h];
            l[j] = (tt + j < nv) ? (lg + bias) * invT : -3e38f;
            lm = fmaxf(lm, l[j]);
        }
        float nm = fmaxf(m, lm);
        float sc = __expf(m - nm);
        float ws = 0.0f; float w[TW];
        #pragma unroll
        for (int j = 0; j < TW; j++) {
            w[j] = (tt + j < nv) ? __expf(l[j] - nm) : 0.0f;
            ws += w[j];
        }
        s = fmaf(s, sc, ws);
        float ax = acc.x * sc, ay = acc.y * sc, az = acc.z * sc, aw = acc.w * sc;
        #pragma unroll
        for (int j = 0; j < TW; j++) {
            ax = fmaf(w[j], e[j].x, ax);
            ay = fmaf(w[j], e[j].y, ay);
            az = fmaf(w[j], e[j].z, az);
            aw = fmaf(w[j], e[j].w, aw);
        }
        acc.x = ax; acc.y = ay; acc.z = az; acc.w = aw;
        m = nm;
        // no second barrier: next tile writes the other spart parity
    }

    // ---- Publish chunk partials ----
    const int pi = (b * NCH + c);
    ((float4*)(g_acc + (size_t)pi * D_))[t] = acc;
    if (lane == 0) {
        g_m[pi * H_ + h] = m;
        g_s[pi * H_ + h] = s;
    }
    __threadfence();
    if (t == 0) s_last = (atomicAdd(&g_cnt[b], 1) == NCH - 1);
    __syncthreads();
    if (!s_last) return;

    // ---- Last CTA for this b: merge + epilogue ----
    if (t == 0) g_cnt[b] = 0;   // self-reset for graph replay determinism

    float mm = -1e30f;
    #pragma unroll
    for (int cc = 0; cc < NCH; cc++)
        mm = fmaxf(mm, __ldcg(&g_m[(b * NCH + cc) * H_ + h]));
    float  ss = 0.0f;
    float4 av = make_float4(0.f, 0.f, 0.f, 0.f);
    #pragma unroll
    for (int cc = 0; cc < NCH; cc++) {
        float mc = __ldcg(&g_m[(b * NCH + cc) * H_ + h]);
        float sc = __expf(mc - mm);
        ss += __ldcg(&g_s[(b * NCH + cc) * H_ + h]) * sc;
        float4 ga = __ldcg((const float4*)(g_acc + (size_t)(b * NCH + cc) * D_) + t);
        av.x = fmaf(ga.x, sc, av.x);
        av.y = fmaf(ga.y, sc, av.y);
        av.z = fmaf(ga.z, sc, av.z);
        av.w = fmaf(ga.w, sc, av.w);
    }
    float inv_s = 1.0f / (ss + 1e-6f);
    float4 wv;
    wv.x = av.x * inv_s; wv.y = av.y * inv_s;
    wv.z = av.z * inv_s; wv.w = av.w * inv_s;

    // per-head gate logit + sum of squares
    float4 gw = __ldg((const float4*)gateW + lane);
    float p = fmaf(wv.x, gw.x, fmaf(wv.y, gw.y, fmaf(wv.z, gw.z, wv.w * gw.w)));
    float q = fmaf(wv.x, wv.x, fmaf(wv.y, wv.y, fmaf(wv.z, wv.z, wv.w * wv.w)));
    #pragma unroll
    for (int o = 16; o > 0; o >>= 1) {
        p += __shfl_xor_sync(0xffffffffu, p, o);
        q += __shfl_xor_sync(0xffffffffu, q, o);
    }
    if (lane == 0) { sgl[h] = p; ssq[h] = q; }
    __syncthreads();

    float gate_l = sgl[h] + gateb[0];
    float sumsq  = ssq[0] + ssq[1] + ssq[2] + ssq[3];
    float valid  = (ss > 0.0f) ? 1.0f : 0.0f;
    float u      = valid / (1.0f + __expf(-gate_l));
    float inv_rms = rsqrtf(sumsq * (1.0f / (float)D_) + 1e-6f);

    float4 rs = __ldg((const float4*)rms_scale + t);
    float4 o1;
    o1.x = wv.x * inv_rms * rs.x;
    o1.y = wv.y * inv_rms * rs.y;
    o1.z = wv.z * inv_rms * rs.z;
    o1.w = wv.w * inv_rms * rs.w;
    ((float4*)(out + b * (2 * D_)))[t] = o1;
    ((float4*)(out + b * (2 * D_) + D_))[t] = make_float4(u, u, u, u);
}

extern "C" void kernel_launch(void* const* d_in, const int* in_sizes, int n_in,
                              void* d_out, int out_size)
{
    const int*   tok        = (const int*)d_in[0];
    const int*   prv        = (const int*)d_in[1];
    const int*   mask       = (const int*)d_in[2];
    const float* embed      = (const float*)d_in[3];
    const float* engram     = (const float*)d_in[4];
    const float* gate_logit = (const float*)d_in[5];
    const float* temp       = (const float*)d_in[6];
    const float* salW       = (const float*)d_in[7];
    const float* salb       = (const float*)d_in[8];
    const float* gateW      = (const float*)d_in[9];
    const float* gateb      = (const float*)d_in[10];
    const float* rms_scale  = (const float*)d_in[11];

    dim3 grid(NCH, B_);
    fused_kernel<<<grid, NT>>>(tok, prv, mask, embed, engram,
                               gate_logit, temp, salW, salb,
                               gateW, gateb, rms_scale, (float*)d_out);
}